// round 1
// baseline (speedup 1.0000x reference)
#include <cuda_runtime.h>
#include <math.h>

#define Bsz   2048
#define Ssz   23
#define Esz   768
#define REDsz 256
#define Hsz   8
#define DHsz  32
#define NLAB  25
#define Mrows (Bsz*Ssz)   // 47104 = 736*64

// ---------------- scratch (allocation-free) ----------------
__device__ float g_h1 [(size_t)Mrows*384];
__device__ float g_h2 [(size_t)Mrows*256];
__device__ float g_red[(size_t)Mrows*256];
__device__ float g_q  [(size_t)Mrows*256];
__device__ float g_k  [(size_t)Mrows*256];
__device__ float g_v  [(size_t)Mrows*256];
__device__ float g_ctx[(size_t)Mrows*256];
__device__ float g_upd[(size_t)Mrows*256];
__device__ unsigned char g_use[Mrows];
__device__ float g_acc;

__device__ __forceinline__ float gelu_f(float x) {
    return 0.5f * x * (1.0f + erff(x * 0.70710678118654752440f));
}

// ---------------- tiled SGEMM: C = act(A @ W^T + bias) ----------------
// A: [M,K] row-major (or gathered rows for MODE==1), W: [N,K] row-major.
// BM=BN=64, BK=16, 256 threads, 4x4 microtile.
// MODE 0: plain store. MODE 1: A-row gathered from cls/missing by mask.
// MODE 2: epilogue select — store C if g_use[m] else g_red[m][n] (N must be 256).
template<int ACT, int MODE>
__global__ void gemm_k(const float* __restrict__ A, const float* __restrict__ W,
                       const float* __restrict__ bias, float* __restrict__ C,
                       int N, int K,
                       const float* __restrict__ cls, const float* __restrict__ miss,
                       const int* __restrict__ mask)
{
    __shared__ float As[16][68];
    __shared__ float Bs[16][68];
    const int tid = threadIdx.x;
    const int tx = tid & 15, ty = tid >> 4;
    const int bm = blockIdx.y * 64;
    const int bn = blockIdx.x * 64;

    const int lrow = tid >> 2;          // 0..63
    const int lk   = (tid & 3) << 2;    // 0,4,8,12

    const float* Arow;
    if (MODE == 1) {
        int r = bm + lrow;
        Arow = (mask[r] > 0) ? (cls + (size_t)r * Esz)
                             : (miss + (size_t)(r % Ssz) * Esz);
    } else {
        Arow = A + (size_t)(bm + lrow) * K;
    }
    const float* Brow = W + (size_t)(bn + lrow) * K;

    float acc[4][4] = {};

    for (int k0 = 0; k0 < K; k0 += 16) {
        float4 av = *reinterpret_cast<const float4*>(Arow + k0 + lk);
        float4 bv = *reinterpret_cast<const float4*>(Brow + k0 + lk);
        As[lk+0][lrow]=av.x; As[lk+1][lrow]=av.y; As[lk+2][lrow]=av.z; As[lk+3][lrow]=av.w;
        Bs[lk+0][lrow]=bv.x; Bs[lk+1][lrow]=bv.y; Bs[lk+2][lrow]=bv.z; Bs[lk+3][lrow]=bv.w;
        __syncthreads();
        #pragma unroll
        for (int kk = 0; kk < 16; kk++) {
            float4 a = *reinterpret_cast<const float4*>(&As[kk][ty << 2]);
            float4 b = *reinterpret_cast<const float4*>(&Bs[kk][tx << 2]);
            float aa[4] = {a.x, a.y, a.z, a.w};
            float bb[4] = {b.x, b.y, b.z, b.w};
            #pragma unroll
            for (int i = 0; i < 4; i++)
                #pragma unroll
                for (int j = 0; j < 4; j++)
                    acc[i][j] += aa[i] * bb[j];
        }
        __syncthreads();
    }

    #pragma unroll
    for (int i = 0; i < 4; i++) {
        int m = bm + (ty << 2) + i;
        int n = bn + (tx << 2);
        float4 o;
        float* po = &o.x;
        #pragma unroll
        for (int j = 0; j < 4; j++) {
            float vv = acc[i][j] + bias[n + j];
            if (ACT == 1) vv = gelu_f(vv);
            po[j] = vv;
        }
        if (MODE == 2) {
            if (!g_use[m])
                o = *reinterpret_cast<const float4*>(&g_red[(size_t)m * 256 + n]);
        }
        *reinterpret_cast<float4*>(&C[(size_t)m * N + n]) = o;
    }
}

// ---------------- LayerNorm over 256, one block per row ----------------
__global__ void ln_k(const float* __restrict__ gam, const float* __restrict__ bet)
{
    int r = blockIdx.x, tid = threadIdx.x;
    float x = g_h2[(size_t)r * 256 + tid];
    __shared__ float sh[256];
    sh[tid] = x; __syncthreads();
    for (int s = 128; s > 0; s >>= 1) { if (tid < s) sh[tid] += sh[tid + s]; __syncthreads(); }
    float mu = sh[0] * (1.0f / 256.0f);
    __syncthreads();
    float d = x - mu;
    sh[tid] = d * d; __syncthreads();
    for (int s = 128; s > 0; s >>= 1) { if (tid < s) sh[tid] += sh[tid + s]; __syncthreads(); }
    float var = sh[0] * (1.0f / 256.0f);
    g_red[(size_t)r * 256 + tid] = d * rsqrtf(var + 1e-5f) * gam[tid] + bet[tid];
}

// ---------------- attention: one block per batch, loop heads ----------------
__global__ void attn_k(const int* __restrict__ mask)
{
    int b = blockIdx.x, tid = threadIdx.x;
    __shared__ float qs[Ssz][DHsz], ks[Ssz][DHsz], vs[Ssz][DHsz];
    __shared__ float sc[Ssz][Ssz + 1];
    __shared__ int exS[Ssz];
    __shared__ int anyS;

    if (b == 0 && tid == 0) g_acc = 0.0f;          // zero loss accumulator each run
    if (tid < Ssz) exS[tid] = (mask[b * Ssz + tid] > 0);
    __syncthreads();
    if (tid == 0) { int a = 0; for (int s = 0; s < Ssz; s++) a |= exS[s]; anyS = a; }
    __syncthreads();
    if (tid < Ssz) g_use[b * Ssz + tid] = (unsigned char)((!exS[tid]) && anyS);

    for (int h = 0; h < Hsz; h++) {
        for (int idx = tid; idx < Ssz * DHsz; idx += 256) {
            int s = idx >> 5, d = idx & 31;
            size_t base = ((size_t)(b * Ssz + s)) * REDsz + h * DHsz + d;
            qs[s][d] = g_q[base]; ks[s][d] = g_k[base]; vs[s][d] = g_v[base];
        }
        __syncthreads();
        for (int idx = tid; idx < Ssz * Ssz; idx += 256) {
            int i = idx / Ssz, j = idx % Ssz;
            float dot = 0.0f;
            #pragma unroll
            for (int d = 0; d < 32; d++) dot += qs[i][d] * ks[j][d];
            sc[i][j] = exS[j] ? dot * 0.17677669529663687f : -1e9f;
        }
        __syncthreads();
        if (tid < Ssz) {
            int i = tid;
            float m = -1e30f;
            for (int j = 0; j < Ssz; j++) m = fmaxf(m, sc[i][j]);
            float sum = 0.0f;
            for (int j = 0; j < Ssz; j++) { float e = expf(sc[i][j] - m); sc[i][j] = e; sum += e; }
            float inv = 1.0f / sum;
            for (int j = 0; j < Ssz; j++) sc[i][j] *= inv;
        }
        __syncthreads();
        for (int idx = tid; idx < Ssz * DHsz; idx += 256) {
            int i = idx >> 5, d = idx & 31;
            float s = 0.0f;
            #pragma unroll
            for (int j = 0; j < Ssz; j++) s += sc[i][j] * vs[j][d];
            g_ctx[((size_t)(b * Ssz + i)) * REDsz + h * DHsz + d] = s;
        }
        __syncthreads();
    }
}

// ---------------- orthogonality loss: one block per batch ----------------
__global__ void loss_k()
{
    int b = blockIdx.x, tid = threadIdx.x;
    __shared__ float X[Ssz][REDsz + 1];   // pad to kill bank conflicts
    __shared__ float inv[Ssz];
    for (int idx = tid; idx < Ssz * REDsz; idx += 256)
        X[idx >> 8][idx & 255] = g_upd[(size_t)b * Ssz * REDsz + idx];
    __syncthreads();
    int w = tid >> 5, lane = tid & 31;
    for (int r = w; r < Ssz; r += 8) {
        float s = 0.0f;
        for (int d = lane; d < 256; d += 32) s += X[r][d] * X[r][d];
        for (int o = 16; o > 0; o >>= 1) s += __shfl_down_sync(0xffffffffu, s, o);
        if (lane == 0) inv[r] = 1.0f / fmaxf(sqrtf(s), 1e-8f);
    }
    __syncthreads();
    float part = 0.0f;
    if (tid < (Ssz * (Ssz - 1)) / 2) {       // 253 pairs i<j
        int p = tid, i = 0;
        while (p >= Ssz - 1 - i) { p -= Ssz - 1 - i; i++; }
        int j = i + 1 + p;
        float dot = 0.0f;
        for (int d = 0; d < 256; d++) dot += X[i][d] * X[j][d];
        float gv = fabsf(dot * inv[i] * inv[j]);
        part = fmaxf(gv - 0.1f, 0.0f) * 2.0f;   // symmetric off-diagonal
    }
    __shared__ float red[256];
    red[tid] = part; __syncthreads();
    for (int s = 128; s > 0; s >>= 1) { if (tid < s) red[tid] += red[tid + s]; __syncthreads(); }
    if (tid == 0) atomicAdd(&g_acc, red[0]);
}

// ---------------- logits: mean over S then Wp ----------------
__global__ void logit_k(const float* __restrict__ Wp, const float* __restrict__ bp,
                        float* __restrict__ out, int loff)
{
    int b = blockIdx.x, tid = threadIdx.x;
    __shared__ float mean[REDsz];
    float s = 0.0f;
    for (int ss = 0; ss < Ssz; ss++)
        s += g_upd[((size_t)(b * Ssz + ss)) * REDsz + tid];
    mean[tid] = s * (1.0f / (float)Ssz);
    __syncthreads();
    if (tid < NLAB) {
        float a = bp[tid];
        const float* wr = Wp + tid * REDsz;
        for (int d = 0; d < REDsz; d++) a += mean[d] * wr[d];
        out[loff + b * NLAB + tid] = a;
    }
}

__global__ void fin_k(float* out, int writeloss)
{
    if (writeloss)
        out[0] = g_acc * (1.0f / ((float)Bsz * Ssz * (Ssz - 1)));
}

// ---------------- launch ----------------
extern "C" void kernel_launch(void* const* d_in, const int* in_sizes, int n_in,
                              void* d_out, int out_size)
{
    const float* cls  = (const float*)d_in[0];
    const int*   mask = (const int*)  d_in[1];
    const float* miss = (const float*)d_in[2];
    const float* W1 = (const float*)d_in[3];  const float* b1 = (const float*)d_in[4];
    const float* W2 = (const float*)d_in[5];  const float* b2 = (const float*)d_in[6];
    const float* lg = (const float*)d_in[7];  const float* lb = (const float*)d_in[8];
    const float* Wq = (const float*)d_in[9];  const float* bq = (const float*)d_in[10];
    const float* Wk = (const float*)d_in[11]; const float* bk = (const float*)d_in[12];
    const float* Wv = (const float*)d_in[13]; const float* bv = (const float*)d_in[14];
    const float* Wo = (const float*)d_in[15]; const float* bo = (const float*)d_in[16];
    const float* Wp = (const float*)d_in[17]; const float* bp = (const float*)d_in[18];
    float* out = (float*)d_out;

    int loff = out_size - Bsz * NLAB;   // expected 1: [loss, logits]
    if (loff < 0) loff = 0;

    float *h1, *h2, *red, *q, *k, *v, *ctx, *upd;
    cudaGetSymbolAddress((void**)&h1,  g_h1);
    cudaGetSymbolAddress((void**)&h2,  g_h2);
    cudaGetSymbolAddress((void**)&red, g_red);
    cudaGetSymbolAddress((void**)&q,   g_q);
    cudaGetSymbolAddress((void**)&k,   g_k);
    cudaGetSymbolAddress((void**)&v,   g_v);
    cudaGetSymbolAddress((void**)&ctx, g_ctx);
    cudaGetSymbolAddress((void**)&upd, g_upd);

    dim3 blk(256);
    // 1) gather + GEMM1 + GELU : [M,768] -> [M,384]
    gemm_k<1,1><<<dim3(384/64, Mrows/64), blk>>>(nullptr, W1, b1, h1, 384, 768, cls, miss, mask);
    // 2) GEMM2 + GELU : [M,384] -> [M,256]
    gemm_k<1,0><<<dim3(256/64, Mrows/64), blk>>>(h1, W2, b2, h2, 256, 384, nullptr, nullptr, nullptr);
    // 3) LayerNorm -> g_red
    ln_k<<<Mrows, blk>>>(lg, lb);
    // 4) Q,K,V projections
    gemm_k<0,0><<<dim3(256/64, Mrows/64), blk>>>(red, Wq, bq, q, 256, 256, nullptr, nullptr, nullptr);
    gemm_k<0,0><<<dim3(256/64, Mrows/64), blk>>>(red, Wk, bk, k, 256, 256, nullptr, nullptr, nullptr);
    gemm_k<0,0><<<dim3(256/64, Mrows/64), blk>>>(red, Wv, bv, v, 256, 256, nullptr, nullptr, nullptr);
    // 5) attention (also computes g_use, zeroes g_acc)
    attn_k<<<Bsz, blk>>>(mask);
    // 6) Wo projection + scatter-select epilogue -> g_upd
    gemm_k<0,2><<<dim3(256/64, Mrows/64), blk>>>(ctx, Wo, bo, upd, 256, 256, nullptr, nullptr, nullptr);
    // 7) orthogonality loss accumulate
    loss_k<<<Bsz, blk>>>();
    // 8) logits
    logit_k<<<Bsz, blk>>>(Wp, bp, out, loff);
    // 9) finalize loss scalar
    fin_k<<<1, 1>>>(out, loff >= 1 ? 1 : 0);
}

// round 2
// speedup vs baseline: 1.3119x; 1.3119x over previous
#include <cuda_runtime.h>
#include <math.h>

#define Bsz   2048
#define Ssz   23
#define Esz   768
#define REDsz 256
#define Hsz   8
#define DHsz  32
#define NLAB  25
#define Mrows (Bsz*Ssz)   // 47104 = 368*128

// ---------------- scratch (allocation-free) ----------------
__device__ float g_h1 [(size_t)Mrows*384];
__device__ float g_h2 [(size_t)Mrows*256];
__device__ float g_red[(size_t)Mrows*256];
__device__ float g_q  [(size_t)Mrows*256];
__device__ float g_k  [(size_t)Mrows*256];
__device__ float g_v  [(size_t)Mrows*256];
__device__ float g_ctx[(size_t)Mrows*256];
__device__ float g_upd[(size_t)Mrows*256];
__device__ unsigned char g_use[Mrows];
__device__ float g_acc;

__device__ __forceinline__ float gelu_f(float x) {
    return 0.5f * x * (1.0f + erff(x * 0.70710678118654752440f));
}

// ---------------- tiled SGEMM: C = act(A @ W^T + bias) ----------------
// BM=BN=128, BK=16, 256 threads, 8x8 microtile, register prefetch.
// MODE 0: plain. MODE 1: A gathered from cls/missing by mask (K=768).
// MODE 2: epilogue select vs g_red (N=256). MODE 3: fused QKV (grid.x=6, N=256 each).
template<int ACT, int MODE>
__global__ void __launch_bounds__(256, 2) gemm128_k(
    const float* __restrict__ A,
    const float* __restrict__ Wa, const float* __restrict__ Wb, const float* __restrict__ Wc,
    const float* __restrict__ ba, const float* __restrict__ bb, const float* __restrict__ bc,
    float* __restrict__ Ca, float* __restrict__ Cb, float* __restrict__ Cc,
    int N, int K,
    const float* __restrict__ cls, const float* __restrict__ miss,
    const int* __restrict__ mask)
{
    __shared__ float As[16][128];
    __shared__ float Bs[16][128];

    const int tid = threadIdx.x;
    const int bm = blockIdx.y * 128;

    const float* W; const float* bias; float* C; int bn;
    if (MODE == 3) {
        int sel = blockIdx.x >> 1;
        W    = sel == 0 ? Wa : sel == 1 ? Wb : Wc;
        bias = sel == 0 ? ba : sel == 1 ? bb : bc;
        C    = sel == 0 ? Ca : sel == 1 ? Cb : Cc;
        bn = (blockIdx.x & 1) * 128;
    } else {
        W = Wa; bias = ba; C = Ca;
        bn = blockIdx.x * 128;
    }

    const int lrow = tid >> 1;           // 0..127
    const int lk   = (tid & 1) << 3;     // 0 or 8

    const float* Arow;
    if (MODE == 1) {
        int r = bm + lrow;
        Arow = (mask[r] > 0) ? (cls + (size_t)r * Esz)
                             : (miss + (size_t)(r % Ssz) * Esz);
    } else {
        Arow = A + (size_t)(bm + lrow) * K;
    }
    const float* Brow = W + (size_t)(bn + lrow) * K;

    const int tx = tid & 15;             // n-index 0..15
    const int ty = tid >> 4;             // m-index 0..15
    const int m0 = ty << 3, n0 = tx << 3;

    float acc[8][8] = {};
    float4 pa0, pa1, pb0, pb1;

    // prefetch tile 0
    pa0 = *reinterpret_cast<const float4*>(Arow + lk);
    pa1 = *reinterpret_cast<const float4*>(Arow + lk + 4);
    pb0 = *reinterpret_cast<const float4*>(Brow + lk);
    pb1 = *reinterpret_cast<const float4*>(Brow + lk + 4);

    for (int k0 = 0; k0 < K; k0 += 16) {
        As[lk+0][lrow]=pa0.x; As[lk+1][lrow]=pa0.y; As[lk+2][lrow]=pa0.z; As[lk+3][lrow]=pa0.w;
        As[lk+4][lrow]=pa1.x; As[lk+5][lrow]=pa1.y; As[lk+6][lrow]=pa1.z; As[lk+7][lrow]=pa1.w;
        Bs[lk+0][lrow]=pb0.x; Bs[lk+1][lrow]=pb0.y; Bs[lk+2][lrow]=pb0.z; Bs[lk+3][lrow]=pb0.w;
        Bs[lk+4][lrow]=pb1.x; Bs[lk+5][lrow]=pb1.y; Bs[lk+6][lrow]=pb1.z; Bs[lk+7][lrow]=pb1.w;
        __syncthreads();

        if (k0 + 16 < K) {
            pa0 = *reinterpret_cast<const float4*>(Arow + k0 + 16 + lk);
            pa1 = *reinterpret_cast<const float4*>(Arow + k0 + 16 + lk + 4);
            pb0 = *reinterpret_cast<const float4*>(Brow + k0 + 16 + lk);
            pb1 = *reinterpret_cast<const float4*>(Brow + k0 + 16 + lk + 4);
        }

        #pragma unroll
        for (int kk = 0; kk < 16; kk++) {
            float4 a0 = *reinterpret_cast<const float4*>(&As[kk][m0]);
            float4 a1 = *reinterpret_cast<const float4*>(&As[kk][m0 + 4]);
            float4 b0 = *reinterpret_cast<const float4*>(&Bs[kk][n0]);
            float4 b1 = *reinterpret_cast<const float4*>(&Bs[kk][n0 + 4]);
            float av[8] = {a0.x,a0.y,a0.z,a0.w,a1.x,a1.y,a1.z,a1.w};
            float bv[8] = {b0.x,b0.y,b0.z,b0.w,b1.x,b1.y,b1.z,b1.w};
            #pragma unroll
            for (int i = 0; i < 8; i++)
                #pragma unroll
                for (int j = 0; j < 8; j++)
                    acc[i][j] += av[i] * bv[j];
        }
        __syncthreads();
    }

    #pragma unroll
    for (int i = 0; i < 8; i++) {
        int m = bm + m0 + i;
        #pragma unroll
        for (int jv = 0; jv < 8; jv += 4) {
            int n = bn + n0 + jv;
            float4 o;
            float* po = &o.x;
            #pragma unroll
            for (int j = 0; j < 4; j++) {
                float vv = acc[i][jv + j] + bias[n + j];
                if (ACT == 1) vv = gelu_f(vv);
                po[j] = vv;
            }
            if (MODE == 2) {
                if (!g_use[m])
                    o = *reinterpret_cast<const float4*>(&g_red[(size_t)m * 256 + n]);
            }
            *reinterpret_cast<float4*>(&C[(size_t)m * N + n]) = o;
        }
    }
}

// ---------------- LayerNorm over 256, one block per row ----------------
__global__ void ln_k(const float* __restrict__ gam, const float* __restrict__ bet)
{
    int r = blockIdx.x, tid = threadIdx.x;
    float x = g_h2[(size_t)r * 256 + tid];
    __shared__ float sh[256];
    sh[tid] = x; __syncthreads();
    for (int s = 128; s > 0; s >>= 1) { if (tid < s) sh[tid] += sh[tid + s]; __syncthreads(); }
    float mu = sh[0] * (1.0f / 256.0f);
    __syncthreads();
    float d = x - mu;
    sh[tid] = d * d; __syncthreads();
    for (int s = 128; s > 0; s >>= 1) { if (tid < s) sh[tid] += sh[tid + s]; __syncthreads(); }
    float var = sh[0] * (1.0f / 256.0f);
    g_red[(size_t)r * 256 + tid] = d * rsqrtf(var + 1e-5f) * gam[tid] + bet[tid];
}

// ---------------- attention: one block per batch, warp per head ----------------
__global__ void attn_k(const int* __restrict__ mask)
{
    int b = blockIdx.x, tid = threadIdx.x;
    int h = tid >> 5, lane = tid & 31;
    __shared__ float qs[Hsz][Ssz][33], ks[Hsz][Ssz][33], vs[Hsz][Ssz][33];
    __shared__ float sc[Hsz][Ssz][Ssz + 1];
    __shared__ int exS[Ssz];
    __shared__ int anyS;

    if (b == 0 && tid == 0) g_acc = 0.0f;
    if (tid < Ssz) exS[tid] = (mask[b * Ssz + tid] > 0);
    __syncthreads();
    if (tid == 0) { int a = 0; for (int s = 0; s < Ssz; s++) a |= exS[s]; anyS = a; }
    __syncthreads();
    if (tid < Ssz) g_use[b * Ssz + tid] = (unsigned char)((!exS[tid]) && anyS);

    // load q,k,v for this warp's head (lane = d, loop s)
    #pragma unroll
    for (int s = 0; s < Ssz; s++) {
        size_t base = ((size_t)(b * Ssz + s)) * REDsz + h * DHsz + lane;
        qs[h][s][lane] = g_q[base];
        ks[h][s][lane] = g_k[base];
        vs[h][s][lane] = g_v[base];
    }
    __syncwarp();

    // scores + mask
    for (int idx = lane; idx < Ssz * Ssz; idx += 32) {
        int i = idx / Ssz, j = idx - i * Ssz;
        float dot = 0.0f;
        #pragma unroll
        for (int d = 0; d < 32; d++) dot += qs[h][i][d] * ks[h][j][d];
        sc[h][i][j] = exS[j] ? dot * 0.17677669529663687f : -1e9f;
    }
    __syncwarp();

    // softmax per row
    if (lane < Ssz) {
        int i = lane;
        float m = -1e30f;
        #pragma unroll
        for (int j = 0; j < Ssz; j++) m = fmaxf(m, sc[h][i][j]);
        float sum = 0.0f;
        #pragma unroll
        for (int j = 0; j < Ssz; j++) { float e = expf(sc[h][i][j] - m); sc[h][i][j] = e; sum += e; }
        float inv = 1.0f / sum;
        #pragma unroll
        for (int j = 0; j < Ssz; j++) sc[h][i][j] *= inv;
    }
    __syncwarp();

    // ctx = attn @ v   (lane = d, loop i)
    #pragma unroll
    for (int i = 0; i < Ssz; i++) {
        float s = 0.0f;
        #pragma unroll
        for (int j = 0; j < Ssz; j++) s += sc[h][i][j] * vs[h][j][lane];
        g_ctx[((size_t)(b * Ssz + i)) * REDsz + h * DHsz + lane] = s;
    }
}

// ---------------- orthogonality loss: one block per batch ----------------
__global__ void loss_k()
{
    int b = blockIdx.x, tid = threadIdx.x;
    __shared__ float X[Ssz][REDsz + 1];
    __shared__ float inv[Ssz];
    for (int idx = tid; idx < Ssz * REDsz; idx += 256)
        X[idx >> 8][idx & 255] = g_upd[(size_t)b * Ssz * REDsz + idx];
    __syncthreads();
    int w = tid >> 5, lane = tid & 31;
    for (int r = w; r < Ssz; r += 8) {
        float s = 0.0f;
        for (int d = lane; d < 256; d += 32) s += X[r][d] * X[r][d];
        for (int o = 16; o > 0; o >>= 1) s += __shfl_down_sync(0xffffffffu, s, o);
        if (lane == 0) inv[r] = 1.0f / fmaxf(sqrtf(s), 1e-8f);
    }
    __syncthreads();
    float part = 0.0f;
    if (tid < (Ssz * (Ssz - 1)) / 2) {
        int p = tid, i = 0;
        while (p >= Ssz - 1 - i) { p -= Ssz - 1 - i; i++; }
        int j = i + 1 + p;
        float dot = 0.0f;
        for (int d = 0; d < 256; d++) dot += X[i][d] * X[j][d];
        float gv = fabsf(dot * inv[i] * inv[j]);
        part = fmaxf(gv - 0.1f, 0.0f) * 2.0f;
    }
    __shared__ float red[256];
    red[tid] = part; __syncthreads();
    for (int s = 128; s > 0; s >>= 1) { if (tid < s) red[tid] += red[tid + s]; __syncthreads(); }
    if (tid == 0) atomicAdd(&g_acc, red[0]);
}

// ---------------- logits: mean over S then Wp ----------------
__global__ void logit_k(const float* __restrict__ Wp, const float* __restrict__ bp,
                        float* __restrict__ out, int loff)
{
    int b = blockIdx.x, tid = threadIdx.x;
    __shared__ float mean[REDsz];
    float s = 0.0f;
    for (int ss = 0; ss < Ssz; ss++)
        s += g_upd[((size_t)(b * Ssz + ss)) * REDsz + tid];
    mean[tid] = s * (1.0f / (float)Ssz);
    __syncthreads();
    if (tid < NLAB) {
        float a = bp[tid];
        const float* wr = Wp + tid * REDsz;
        for (int d = 0; d < REDsz; d++) a += mean[d] * wr[d];
        out[loff + b * NLAB + tid] = a;
    }
}

__global__ void fin_k(float* out, int writeloss)
{
    if (writeloss)
        out[0] = g_acc * (1.0f / ((float)Bsz * Ssz * (Ssz - 1)));
}

// ---------------- launch ----------------
extern "C" void kernel_launch(void* const* d_in, const int* in_sizes, int n_in,
                              void* d_out, int out_size)
{
    const float* cls  = (const float*)d_in[0];
    const int*   mask = (const int*)  d_in[1];
    const float* miss = (const float*)d_in[2];
    const float* W1 = (const float*)d_in[3];  const float* b1 = (const float*)d_in[4];
    const float* W2 = (const float*)d_in[5];  const float* b2 = (const float*)d_in[6];
    const float* lg = (const float*)d_in[7];  const float* lb = (const float*)d_in[8];
    const float* Wq = (const float*)d_in[9];  const float* bq = (const float*)d_in[10];
    const float* Wk = (const float*)d_in[11]; const float* bk = (const float*)d_in[12];
    const float* Wv = (const float*)d_in[13]; const float* bv = (const float*)d_in[14];
    const float* Wo = (const float*)d_in[15]; const float* bo = (const float*)d_in[16];
    const float* Wp = (const float*)d_in[17]; const float* bp = (const float*)d_in[18];
    float* out = (float*)d_out;

    int loff = out_size - Bsz * NLAB;
    if (loff < 0) loff = 0;

    float *h1, *h2, *red, *q, *k, *v, *ctx, *upd;
    cudaGetSymbolAddress((void**)&h1,  g_h1);
    cudaGetSymbolAddress((void**)&h2,  g_h2);
    cudaGetSymbolAddress((void**)&red, g_red);
    cudaGetSymbolAddress((void**)&q,   g_q);
    cudaGetSymbolAddress((void**)&k,   g_k);
    cudaGetSymbolAddress((void**)&v,   g_v);
    cudaGetSymbolAddress((void**)&ctx, g_ctx);
    cudaGetSymbolAddress((void**)&upd, g_upd);

    dim3 blk(256);
    // 1) gather + GEMM1 + GELU : [M,768] -> [M,384]
    gemm128_k<1,1><<<dim3(384/128, Mrows/128), blk>>>(
        nullptr, W1, nullptr, nullptr, b1, nullptr, nullptr,
        h1, nullptr, nullptr, 384, 768, cls, miss, mask);
    // 2) GEMM2 + GELU : [M,384] -> [M,256]
    gemm128_k<1,0><<<dim3(256/128, Mrows/128), blk>>>(
        h1, W2, nullptr, nullptr, b2, nullptr, nullptr,
        h2, nullptr, nullptr, 256, 384, nullptr, nullptr, nullptr);
    // 3) LayerNorm -> g_red
    ln_k<<<Mrows, blk>>>(lg, lb);
    // 4) fused QKV projections
    gemm128_k<0,3><<<dim3(6, Mrows/128), blk>>>(
        red, Wq, Wk, Wv, bq, bk, bv,
        q, k, v, 256, 256, nullptr, nullptr, nullptr);
    // 5) attention (also computes g_use, zeroes g_acc)
    attn_k<<<Bsz, blk>>>(mask);
    // 6) Wo projection + scatter-select epilogue -> g_upd
    gemm128_k<0,2><<<dim3(256/128, Mrows/128), blk>>>(
        ctx, Wo, nullptr, nullptr, bo, nullptr, nullptr,
        upd, nullptr, nullptr, 256, 256, nullptr, nullptr, nullptr);
    // 7) orthogonality loss accumulate
    loss_k<<<Bsz, blk>>>();
    // 8) logits
    logit_k<<<Bsz, blk>>>(Wp, bp, out, loff);
    // 9) finalize loss scalar
    fin_k<<<1, 1>>>(out, loff >= 1 ? 1 : 0);
}

// round 3
// speedup vs baseline: 1.4396x; 1.0973x over previous
#include <cuda_runtime.h>
#include <math.h>

#define Bsz   2048
#define Ssz   23
#define Esz   768
#define REDsz 256
#define Hsz   8
#define DHsz  32
#define NLAB  25
#define Mrows (Bsz*Ssz)   // 47104 = 368*128

// ---------------- scratch (allocation-free) ----------------
__device__ float g_h1 [(size_t)Mrows*384];
__device__ float g_h2 [(size_t)Mrows*256];
__device__ float g_red[(size_t)Mrows*256];
__device__ float g_q  [(size_t)Mrows*256];
__device__ float g_k  [(size_t)Mrows*256];
__device__ float g_v  [(size_t)Mrows*256];
__device__ float g_ctx[(size_t)Mrows*256];
__device__ float g_upd[(size_t)Mrows*256];
__device__ unsigned char g_use[Mrows];
__device__ float g_acc;

__device__ __forceinline__ float gelu_f(float x) {
    return 0.5f * x * (1.0f + erff(x * 0.70710678118654752440f));
}

// ---------------- tiled SGEMM: C = act(A @ W^T + bias) ----------------
// BM=BN=128, BK=16, 256 threads, 8x8 microtile in SPLIT-QUAD layout:
// thread owns m in {ty*4..+3, 64+ty*4..+3}, n in {tx*4..+3, 64+tx*4..+3}.
// B-fragment float4 reads are 256B-contiguous per warp -> conflict-free.
// MODE 0: plain. MODE 1: A gathered from cls/missing by mask (K=768).
// MODE 2: epilogue select vs g_red (N=256). MODE 3: fused QKV (grid.x=6).
template<int ACT, int MODE>
__global__ void __launch_bounds__(256, 2) gemm128_k(
    const float* __restrict__ A,
    const float* __restrict__ Wa, const float* __restrict__ Wb, const float* __restrict__ Wc,
    const float* __restrict__ ba, const float* __restrict__ bb, const float* __restrict__ bc,
    float* __restrict__ Ca, float* __restrict__ Cb, float* __restrict__ Cc,
    int N, int K,
    const float* __restrict__ cls, const float* __restrict__ miss,
    const int* __restrict__ mask)
{
    __shared__ float As[16][128];
    __shared__ float Bs[16][128];

    const int tid = threadIdx.x;
    const int bm = blockIdx.y * 128;

    const float* W; const float* bias; float* C; int bn;
    if (MODE == 3) {
        int sel = blockIdx.x >> 1;
        W    = sel == 0 ? Wa : sel == 1 ? Wb : Wc;
        bias = sel == 0 ? ba : sel == 1 ? bb : bc;
        C    = sel == 0 ? Ca : sel == 1 ? Cb : Cc;
        bn = (blockIdx.x & 1) * 128;
    } else {
        W = Wa; bias = ba; C = Ca;
        bn = blockIdx.x * 128;
    }

    const int lrow = tid >> 1;           // 0..127
    const int lk   = (tid & 1) << 3;     // 0 or 8

    const float* Arow;
    if (MODE == 1) {
        int r = bm + lrow;
        Arow = (mask[r] > 0) ? (cls + (size_t)r * Esz)
                             : (miss + (size_t)(r % Ssz) * Esz);
    } else {
        Arow = A + (size_t)(bm + lrow) * K;
    }
    const float* Brow = W + (size_t)(bn + lrow) * K;

    const int tx = tid & 15;             // 0..15
    const int ty = tid >> 4;             // 0..15
    const int mA = ty << 2;              // first m-quad
    const int nA = tx << 2;              // first n-quad
    // second quads at +64

    float acc[8][8] = {};
    float4 pa0, pa1, pb0, pb1;

    // prefetch tile 0
    pa0 = *reinterpret_cast<const float4*>(Arow + lk);
    pa1 = *reinterpret_cast<const float4*>(Arow + lk + 4);
    pb0 = *reinterpret_cast<const float4*>(Brow + lk);
    pb1 = *reinterpret_cast<const float4*>(Brow + lk + 4);

    for (int k0 = 0; k0 < K; k0 += 16) {
        As[lk+0][lrow]=pa0.x; As[lk+1][lrow]=pa0.y; As[lk+2][lrow]=pa0.z; As[lk+3][lrow]=pa0.w;
        As[lk+4][lrow]=pa1.x; As[lk+5][lrow]=pa1.y; As[lk+6][lrow]=pa1.z; As[lk+7][lrow]=pa1.w;
        Bs[lk+0][lrow]=pb0.x; Bs[lk+1][lrow]=pb0.y; Bs[lk+2][lrow]=pb0.z; Bs[lk+3][lrow]=pb0.w;
        Bs[lk+4][lrow]=pb1.x; Bs[lk+5][lrow]=pb1.y; Bs[lk+6][lrow]=pb1.z; Bs[lk+7][lrow]=pb1.w;
        __syncthreads();

        if (k0 + 16 < K) {
            pa0 = *reinterpret_cast<const float4*>(Arow + k0 + 16 + lk);
            pa1 = *reinterpret_cast<const float4*>(Arow + k0 + 16 + lk + 4);
            pb0 = *reinterpret_cast<const float4*>(Brow + k0 + 16 + lk);
            pb1 = *reinterpret_cast<const float4*>(Brow + k0 + 16 + lk + 4);
        }

        #pragma unroll
        for (int kk = 0; kk < 16; kk++) {
            float4 a0 = *reinterpret_cast<const float4*>(&As[kk][mA]);
            float4 a1 = *reinterpret_cast<const float4*>(&As[kk][mA + 64]);
            float4 b0 = *reinterpret_cast<const float4*>(&Bs[kk][nA]);
            float4 b1 = *reinterpret_cast<const float4*>(&Bs[kk][nA + 64]);
            float av[8] = {a0.x,a0.y,a0.z,a0.w,a1.x,a1.y,a1.z,a1.w};
            float bv[8] = {b0.x,b0.y,b0.z,b0.w,b1.x,b1.y,b1.z,b1.w};
            #pragma unroll
            for (int i = 0; i < 8; i++)
                #pragma unroll
                for (int j = 0; j < 8; j++)
                    acc[i][j] += av[i] * bv[j];
        }
        __syncthreads();
    }

    #pragma unroll
    for (int qi = 0; qi < 2; qi++) {
        #pragma unroll
        for (int i = 0; i < 4; i++) {
            int m = bm + qi * 64 + mA + i;
            #pragma unroll
            for (int qj = 0; qj < 2; qj++) {
                int n = bn + qj * 64 + nA;
                float4 o;
                float* po = &o.x;
                #pragma unroll
                for (int j = 0; j < 4; j++) {
                    float vv = acc[qi*4 + i][qj*4 + j] + bias[n + j];
                    if (ACT == 1) vv = gelu_f(vv);
                    po[j] = vv;
                }
                if (MODE == 2) {
                    if (!g_use[m])
                        o = *reinterpret_cast<const float4*>(&g_red[(size_t)m * 256 + n]);
                }
                *reinterpret_cast<float4*>(&C[(size_t)m * N + n]) = o;
            }
        }
    }
}

// ---------------- LayerNorm over 256, one block per row ----------------
__global__ void ln_k(const float* __restrict__ gam, const float* __restrict__ bet)
{
    int r = blockIdx.x, tid = threadIdx.x;
    float x = g_h2[(size_t)r * 256 + tid];
    __shared__ float sh[256];
    sh[tid] = x; __syncthreads();
    for (int s = 128; s > 0; s >>= 1) { if (tid < s) sh[tid] += sh[tid + s]; __syncthreads(); }
    float mu = sh[0] * (1.0f / 256.0f);
    __syncthreads();
    float d = x - mu;
    sh[tid] = d * d; __syncthreads();
    for (int s = 128; s > 0; s >>= 1) { if (tid < s) sh[tid] += sh[tid + s]; __syncthreads(); }
    float var = sh[0] * (1.0f / 256.0f);
    g_red[(size_t)r * 256 + tid] = d * rsqrtf(var + 1e-5f) * gam[tid] + bet[tid];
}

// ---------------- attention: one block per batch, warp per head ----------------
__global__ void attn_k(const int* __restrict__ mask)
{
    int b = blockIdx.x, tid = threadIdx.x;
    int h = tid >> 5, lane = tid & 31;
    __shared__ float qs[Hsz][Ssz][33], ks[Hsz][Ssz][33], vs[Hsz][Ssz][33];
    __shared__ float sc[Hsz][Ssz][Ssz + 1];
    __shared__ int exS[Ssz];
    __shared__ int anyS;

    if (b == 0 && tid == 0) g_acc = 0.0f;
    if (tid < Ssz) exS[tid] = (mask[b * Ssz + tid] > 0);
    __syncthreads();
    if (tid == 0) { int a = 0; for (int s = 0; s < Ssz; s++) a |= exS[s]; anyS = a; }
    __syncthreads();
    if (tid < Ssz) g_use[b * Ssz + tid] = (unsigned char)((!exS[tid]) && anyS);

    #pragma unroll
    for (int s = 0; s < Ssz; s++) {
        size_t base = ((size_t)(b * Ssz + s)) * REDsz + h * DHsz + lane;
        qs[h][s][lane] = g_q[base];
        ks[h][s][lane] = g_k[base];
        vs[h][s][lane] = g_v[base];
    }
    __syncwarp();

    for (int idx = lane; idx < Ssz * Ssz; idx += 32) {
        int i = idx / Ssz, j = idx - i * Ssz;
        float dot = 0.0f;
        #pragma unroll
        for (int d = 0; d < 32; d++) dot += qs[h][i][d] * ks[h][j][d];
        sc[h][i][j] = exS[j] ? dot * 0.17677669529663687f : -1e9f;
    }
    __syncwarp();

    if (lane < Ssz) {
        int i = lane;
        float m = -1e30f;
        #pragma unroll
        for (int j = 0; j < Ssz; j++) m = fmaxf(m, sc[h][i][j]);
        float sum = 0.0f;
        #pragma unroll
        for (int j = 0; j < Ssz; j++) { float e = expf(sc[h][i][j] - m); sc[h][i][j] = e; sum += e; }
        float inv = 1.0f / sum;
        #pragma unroll
        for (int j = 0; j < Ssz; j++) sc[h][i][j] *= inv;
    }
    __syncwarp();

    #pragma unroll
    for (int i = 0; i < Ssz; i++) {
        float s = 0.0f;
        #pragma unroll
        for (int j = 0; j < Ssz; j++) s += sc[h][i][j] * vs[h][j][lane];
        g_ctx[((size_t)(b * Ssz + i)) * REDsz + h * DHsz + lane] = s;
    }
}

// ---------------- orthogonality loss: one block per batch ----------------
__global__ void loss_k()
{
    int b = blockIdx.x, tid = threadIdx.x;
    __shared__ float X[Ssz][REDsz + 1];
    __shared__ float inv[Ssz];
    for (int idx = tid; idx < Ssz * REDsz; idx += 256)
        X[idx >> 8][idx & 255] = g_upd[(size_t)b * Ssz * REDsz + idx];
    __syncthreads();
    int w = tid >> 5, lane = tid & 31;
    for (int r = w; r < Ssz; r += 8) {
        float s = 0.0f;
        for (int d = lane; d < 256; d += 32) s += X[r][d] * X[r][d];
        for (int o = 16; o > 0; o >>= 1) s += __shfl_down_sync(0xffffffffu, s, o);
        if (lane == 0) inv[r] = 1.0f / fmaxf(sqrtf(s), 1e-8f);
    }
    __syncthreads();
    float part = 0.0f;
    if (tid < (Ssz * (Ssz - 1)) / 2) {
        int p = tid, i = 0;
        while (p >= Ssz - 1 - i) { p -= Ssz - 1 - i; i++; }
        int j = i + 1 + p;
        float dot = 0.0f;
        for (int d = 0; d < 256; d++) dot += X[i][d] * X[j][d];
        float gv = fabsf(dot * inv[i] * inv[j]);
        part = fmaxf(gv - 0.1f, 0.0f) * 2.0f;
    }
    __shared__ float red[256];
    red[tid] = part; __syncthreads();
    for (int s = 128; s > 0; s >>= 1) { if (tid < s) red[tid] += red[tid + s]; __syncthreads(); }
    if (tid == 0) atomicAdd(&g_acc, red[0]);
}

// ---------------- logits: mean over S then Wp ----------------
__global__ void logit_k(const float* __restrict__ Wp, const float* __restrict__ bp,
                        float* __restrict__ out, int loff)
{
    int b = blockIdx.x, tid = threadIdx.x;
    __shared__ float mean[REDsz];
    float s = 0.0f;
    for (int ss = 0; ss < Ssz; ss++)
        s += g_upd[((size_t)(b * Ssz + ss)) * REDsz + tid];
    mean[tid] = s * (1.0f / (float)Ssz);
    __syncthreads();
    if (tid < NLAB) {
        float a = bp[tid];
        const float* wr = Wp + tid * REDsz;
        for (int d = 0; d < REDsz; d++) a += mean[d] * wr[d];
        out[loff + b * NLAB + tid] = a;
    }
}

__global__ void fin_k(float* out, int writeloss)
{
    if (writeloss)
        out[0] = g_acc * (1.0f / ((float)Bsz * Ssz * (Ssz - 1)));
}

// ---------------- launch ----------------
extern "C" void kernel_launch(void* const* d_in, const int* in_sizes, int n_in,
                              void* d_out, int out_size)
{
    const float* cls  = (const float*)d_in[0];
    const int*   mask = (const int*)  d_in[1];
    const float* miss = (const float*)d_in[2];
    const float* W1 = (const float*)d_in[3];  const float* b1 = (const float*)d_in[4];
    const float* W2 = (const float*)d_in[5];  const float* b2 = (const float*)d_in[6];
    const float* lg = (const float*)d_in[7];  const float* lb = (const float*)d_in[8];
    const float* Wq = (const float*)d_in[9];  const float* bq = (const float*)d_in[10];
    const float* Wk = (const float*)d_in[11]; const float* bk = (const float*)d_in[12];
    const float* Wv = (const float*)d_in[13]; const float* bv = (const float*)d_in[14];
    const float* Wo = (const float*)d_in[15]; const float* bo = (const float*)d_in[16];
    const float* Wp = (const float*)d_in[17]; const float* bp = (const float*)d_in[18];
    float* out = (float*)d_out;

    int loff = out_size - Bsz * NLAB;
    if (loff < 0) loff = 0;

    float *h1, *h2, *red, *q, *k, *v, *ctx, *upd;
    cudaGetSymbolAddress((void**)&h1,  g_h1);
    cudaGetSymbolAddress((void**)&h2,  g_h2);
    cudaGetSymbolAddress((void**)&red, g_red);
    cudaGetSymbolAddress((void**)&q,   g_q);
    cudaGetSymbolAddress((void**)&k,   g_k);
    cudaGetSymbolAddress((void**)&v,   g_v);
    cudaGetSymbolAddress((void**)&ctx, g_ctx);
    cudaGetSymbolAddress((void**)&upd, g_upd);

    dim3 blk(256);
    // 1) gather + GEMM1 + GELU : [M,768] -> [M,384]
    gemm128_k<1,1><<<dim3(384/128, Mrows/128), blk>>>(
        nullptr, W1, nullptr, nullptr, b1, nullptr, nullptr,
        h1, nullptr, nullptr, 384, 768, cls, miss, mask);
    // 2) GEMM2 + GELU : [M,384] -> [M,256]
    gemm128_k<1,0><<<dim3(256/128, Mrows/128), blk>>>(
        h1, W2, nullptr, nullptr, b2, nullptr, nullptr,
        h2, nullptr, nullptr, 256, 384, nullptr, nullptr, nullptr);
    // 3) LayerNorm -> g_red
    ln_k<<<Mrows, blk>>>(lg, lb);
    // 4) fused QKV projections
    gemm128_k<0,3><<<dim3(6, Mrows/128), blk>>>(
        red, Wq, Wk, Wv, bq, bk, bv,
        q, k, v, 256, 256, nullptr, nullptr, nullptr);
    // 5) attention (also computes g_use, zeroes g_acc)
    attn_k<<<Bsz, blk>>>(mask);
    // 6) Wo projection + scatter-select epilogue -> g_upd
    gemm128_k<0,2><<<dim3(256/128, Mrows/128), blk>>>(
        ctx, Wo, nullptr, nullptr, bo, nullptr, nullptr,
        upd, nullptr, nullptr, 256, 256, nullptr, nullptr, nullptr);
    // 7) orthogonality loss accumulate
    loss_k<<<Bsz, blk>>>();
    // 8) logits
    logit_k<<<Bsz, blk>>>(Wp, bp, out, loff);
    // 9) finalize loss scalar
    fin_k<<<1, 1>>>(out, loff >= 1 ? 1 : 0);
}